// round 3
// baseline (speedup 1.0000x reference)
#include <cuda_runtime.h>
#include <cstdint>
#include <cmath>

#define PP 512
#define CC 65536
#define TILE_C 64
#define KB 16
#define AS_LD 516          // 512 + 4 floats pad (keeps 16B alignment, de-conflicts STS)
#define NTHREADS 256
#define SMEM_FLOATS (PP * TILE_C + KB * AS_LD + 32 * TILE_C + TILE_C)
#define SMEM_BYTES (SMEM_FLOATS * 4)

// A transposed: g_At[p * PP + r] = softmax_p(rule_weights[r, 0, p])
__device__ float g_At[PP * PP];

// ---------------------------------------------------------------------------
// packed fp32x2 helpers (sm_103a dual-rate FFMA path, PTX-only per quickref)
// ---------------------------------------------------------------------------
__device__ __forceinline__ unsigned long long dup2(float x) {
    unsigned long long r;
    asm("mov.b64 %0, {%1, %1};" : "=l"(r) : "f"(x));
    return r;
}
__device__ __forceinline__ void fma2(unsigned long long& d,
                                     unsigned long long a,
                                     unsigned long long b) {
    asm("fma.rn.f32x2 %0, %1, %2, %0;" : "+l"(d) : "l"(a), "l"(b));
}
__device__ __forceinline__ void unpack2(unsigned long long v, float& lo, float& hi) {
    asm("mov.b64 {%0, %1}, %2;" : "=f"(lo), "=f"(hi) : "l"(v));
}

// ---------------------------------------------------------------------------
// Kernel 1: row-wise softmax of rule_weights[r,0,:] -> transposed g_At[p][r]
// ---------------------------------------------------------------------------
__global__ void ilp_softmax_kernel(const float* __restrict__ rw) {
    const int r = blockIdx.x;
    const int tid = threadIdx.x;
    const float* wrow = rw + r * PP;   // L = 1, so [r, 0, :]

    __shared__ float wbuf[8];
    __shared__ float s_mx, s_inv;

    float v0 = wrow[tid];
    float v1 = wrow[tid + 256];

    // block max
    float m = fmaxf(v0, v1);
    #pragma unroll
    for (int o = 16; o; o >>= 1) m = fmaxf(m, __shfl_xor_sync(0xffffffffu, m, o));
    if ((tid & 31) == 0) wbuf[tid >> 5] = m;
    __syncthreads();
    if (tid == 0) {
        float mm = wbuf[0];
        #pragma unroll
        for (int w = 1; w < 8; ++w) mm = fmaxf(mm, wbuf[w]);
        s_mx = mm;
    }
    __syncthreads();

    // block sum of exp
    float e0 = expf(v0 - s_mx);
    float e1 = expf(v1 - s_mx);
    float s = e0 + e1;
    #pragma unroll
    for (int o = 16; o; o >>= 1) s += __shfl_xor_sync(0xffffffffu, s, o);
    if ((tid & 31) == 0) wbuf[tid >> 5] = s;
    __syncthreads();
    if (tid == 0) {
        float ss = 0.f;
        #pragma unroll
        for (int w = 0; w < 8; ++w) ss += wbuf[w];
        s_inv = 1.0f / ss;
    }
    __syncthreads();

    g_At[(size_t)tid * PP + r]         = e0 * s_inv;
    g_At[(size_t)(tid + 256) * PP + r] = e1 * s_inv;
}

// ---------------------------------------------------------------------------
// Kernel 2: per-column-tile fused forward chaining.
//   Per CTA: 64 columns, f0 tile in SMEM (512x64 fp32), running column scalar
//   M[64]. Each iteration: colmax over r of A @ max(f0, M), M = max(M, .).
//   GEMM: 256 threads, each owns 16 rows x 8 cols -> 64 f32x2 accumulators.
// ---------------------------------------------------------------------------
__global__ void __launch_bounds__(NTHREADS, 1)
ilp_main_kernel(const float* __restrict__ facts,
                const int* __restrict__ nit_ptr,
                float* __restrict__ out) {
    extern __shared__ float smem[];
    float* xs  = smem;                        // [512][64] f0 tile
    float* As  = xs + PP * TILE_C;            // [16][516] A stage
    float* red = As + KB * AS_LD;             // [32][64] partial col-max
    float* Msm = red + 32 * TILE_C;           // [64]

    const int tid   = threadIdx.x;
    const int cbase = blockIdx.x * TILE_C;

    // loader mapping: 16 float4-cols x 16 rows, striding rows by 16
    const int col4 = tid & 15;
    const int prow = tid >> 4;                // also the A-stage k row (0..15)

    // load f0 tile (coalesced 256B per 16-lane group)
    #pragma unroll
    for (int p = prow; p < PP; p += 16) {
        *(float4*)&xs[p * TILE_C + col4 * 4] =
            *(const float4*)&facts[(size_t)p * CC + cbase + col4 * 4];
    }
    if (tid < TILE_C) Msm[tid] = -INFINITY;
    __syncthreads();

    const int n_it = nit_ptr ? *nit_ptr : 3;

    // compute mapping: 32 thread-rows x 8 thread-cols
    const int row_t = tid >> 3;               // 0..31
    const int col_t = tid & 7;                // 0..7
    const int r0 = row_t * 16;
    const int c0 = col_t * 8;

    const float4* At4 = (const float4*)g_At;

    for (int it = 0; it < n_it; ++it) {
        float Mreg[8];
        #pragma unroll
        for (int j = 0; j < 8; ++j) Mreg[j] = Msm[c0 + j];

        unsigned long long acc[8][8];
        #pragma unroll
        for (int i = 0; i < 8; ++i)
            #pragma unroll
            for (int j = 0; j < 8; ++j) acc[i][j] = 0ull;

        // prefetch first A stage into registers
        float4 areg[8];
        #pragma unroll
        for (int j = 0; j < 8; ++j)
            areg[j] = At4[(size_t)prow * (PP / 4) + col4 + j * 16];

        for (int kb = 0; kb < PP; kb += KB) {
            __syncthreads();   // previous stage consumers done
            #pragma unroll
            for (int j = 0; j < 8; ++j)
                *(float4*)&As[prow * AS_LD + (col4 + j * 16) * 4] = areg[j];
            if (kb + KB < PP) {
                #pragma unroll
                for (int j = 0; j < 8; ++j)
                    areg[j] = At4[(size_t)(kb + KB + prow) * (PP / 4) + col4 + j * 16];
            }
            __syncthreads();   // As visible

            #pragma unroll 2
            for (int kk = 0; kk < KB; ++kk) {
                const float* arow = &As[kk * AS_LD + r0];
                ulonglong2 av0 = *(const ulonglong2*)(arow + 0);
                ulonglong2 av1 = *(const ulonglong2*)(arow + 4);
                ulonglong2 av2 = *(const ulonglong2*)(arow + 8);
                ulonglong2 av3 = *(const ulonglong2*)(arow + 12);

                const float4* xr = (const float4*)&xs[(kb + kk) * TILE_C + c0];
                float4 x0 = xr[0];
                float4 x1 = xr[1];

                // x_eff = max(f0, M) fused at read (ALU pipe), then lane-dup
                unsigned long long xd[8];
                xd[0] = dup2(fmaxf(x0.x, Mreg[0]));
                xd[1] = dup2(fmaxf(x0.y, Mreg[1]));
                xd[2] = dup2(fmaxf(x0.z, Mreg[2]));
                xd[3] = dup2(fmaxf(x0.w, Mreg[3]));
                xd[4] = dup2(fmaxf(x1.x, Mreg[4]));
                xd[5] = dup2(fmaxf(x1.y, Mreg[5]));
                xd[6] = dup2(fmaxf(x1.z, Mreg[6]));
                xd[7] = dup2(fmaxf(x1.w, Mreg[7]));

                // row pairs come packed for free from the 16B A loads
                unsigned long long a2[8] = {av0.x, av0.y, av1.x, av1.y,
                                            av2.x, av2.y, av3.x, av3.y};

                #pragma unroll
                for (int i = 0; i < 8; ++i) {
                    #pragma unroll
                    for (int j = 0; j < 8; ++j) fma2(acc[i][j], a2[i], xd[j]);
                }
            }
        }

        // per-thread column max over its 16 rows
        #pragma unroll
        for (int j = 0; j < 8; ++j) {
            float m = -INFINITY;
            #pragma unroll
            for (int i = 0; i < 8; ++i) {
                float lo, hi;
                unpack2(acc[i][j], lo, hi);
                m = fmaxf(m, fmaxf(lo, hi));
            }
            red[row_t * TILE_C + c0 + j] = m;
        }
        __syncthreads();
        if (tid < TILE_C) {
            float m = Msm[tid];
            #pragma unroll
            for (int t = 0; t < 32; ++t) m = fmaxf(m, red[t * TILE_C + tid]);
            Msm[tid] = m;
        }
        __syncthreads();
    }

    // output: max(f0, M_final), coalesced float4 stores
    #pragma unroll
    for (int p = prow; p < PP; p += 16) {
        float4 v = *(float4*)&xs[p * TILE_C + col4 * 4];
        v.x = fmaxf(v.x, Msm[col4 * 4 + 0]);
        v.y = fmaxf(v.y, Msm[col4 * 4 + 1]);
        v.z = fmaxf(v.z, Msm[col4 * 4 + 2]);
        v.w = fmaxf(v.w, Msm[col4 * 4 + 3]);
        *(float4*)&out[(size_t)p * CC + cbase + col4 * 4] = v;
    }
}

// ---------------------------------------------------------------------------
extern "C" void kernel_launch(void* const* d_in, const int* in_sizes, int n_in,
                              void* d_out, int out_size) {
    (void)in_sizes; (void)out_size;
    const float* facts = (const float*)d_in[0];
    const float* rw    = (const float*)d_in[1];
    const int*   nit   = (n_in > 2) ? (const int*)d_in[2] : nullptr;
    float* out = (float*)d_out;

    cudaFuncSetAttribute(ilp_main_kernel,
                         cudaFuncAttributeMaxDynamicSharedMemorySize, SMEM_BYTES);

    ilp_softmax_kernel<<<PP, NTHREADS>>>(rw);
    ilp_main_kernel<<<CC / TILE_C, NTHREADS, SMEM_BYTES>>>(facts, nit, out);
}

// round 5
// speedup vs baseline: 4.1499x; 4.1499x over previous
#include <cuda_runtime.h>
#include <cstdint>
#include <cmath>

#define PP 512
#define CC 65536
#define TILE_C 64
#define NTHREADS 256
#define XS_BYTES (PP * TILE_C * 4)

// A: softmaxed, tf32-rounded, stored in m16n8k8 A-fragment order:
//   g_A[(((m_tile*64) + k8)*32 + lane)*4 + slot],  slot = a0..a3
__device__ float g_A[PP * PP];

__device__ __forceinline__ uint32_t tf32r(float x) {
    uint32_t y;
    asm("cvt.rna.tf32.f32 %0, %1;" : "=r"(y) : "f"(x));
    return y;
}

// ---------------------------------------------------------------------------
// Kernel 1: softmax rows of rule_weights[r,0,:] -> g_A (tf32, frag-packed)
// ---------------------------------------------------------------------------
__global__ void ilp_softmax_kernel(const float* __restrict__ rw) {
    const int r = blockIdx.x;
    const int tid = threadIdx.x;
    const float* wrow = rw + r * PP;

    __shared__ float wbuf[8];
    __shared__ float s_mx, s_inv;

    float v0 = wrow[tid];
    float v1 = wrow[tid + 256];

    float m = fmaxf(v0, v1);
    #pragma unroll
    for (int o = 16; o; o >>= 1) m = fmaxf(m, __shfl_xor_sync(0xffffffffu, m, o));
    if ((tid & 31) == 0) wbuf[tid >> 5] = m;
    __syncthreads();
    if (tid == 0) {
        float mm = wbuf[0];
        #pragma unroll
        for (int w = 1; w < 8; ++w) mm = fmaxf(mm, wbuf[w]);
        s_mx = mm;
    }
    __syncthreads();

    float e0 = expf(v0 - s_mx);
    float e1 = expf(v1 - s_mx);
    float s = e0 + e1;
    #pragma unroll
    for (int o = 16; o; o >>= 1) s += __shfl_xor_sync(0xffffffffu, s, o);
    if ((tid & 31) == 0) wbuf[tid >> 5] = s;
    __syncthreads();
    if (tid == 0) {
        float ss = 0.f;
        #pragma unroll
        for (int w = 0; w < 8; ++w) ss += wbuf[w];
        s_inv = 1.0f / ss;
    }
    __syncthreads();

    const int mt = r >> 4;
    #pragma unroll
    for (int h = 0; h < 2; ++h) {
        const int p = tid + h * 256;                 // k index
        const float val = (h ? e1 : e0) * s_inv;
        const int k8   = p >> 3;
        const int lane = ((r & 7) << 2) | (p & 3);
        const int slot = ((r >> 3) & 1) | (((p >> 2) & 1) << 1);
        g_A[(((mt << 6) | k8) * 32 + lane) * 4 + slot] = __uint_as_float(tf32r(val));
    }
}

// ---------------------------------------------------------------------------
// Kernel 2: fused forward chaining via mma.sync m16n8k8 tf32.
//   CTA: 64 columns. xs in SMEM in B-frag-packed layout. Warp w covers
//   rows [64w, 64w+64): 4 m-tiles x 8 n-tiles -> 128 fp32 accumulators.
// ---------------------------------------------------------------------------
__global__ void __launch_bounds__(NTHREADS, 1)
ilp_mma_kernel(const float* __restrict__ facts,
               const int* __restrict__ nit_ptr,
               float* __restrict__ out) {
    extern __shared__ float xs[];                    // [k8][n_tile][lane][2]
    __shared__ float s_M[TILE_C];
    __shared__ float s_red[8][TILE_C];

    const int tid  = threadIdx.x;
    const int wid  = tid >> 5;
    const int lane = tid & 31;
    const int cbase = blockIdx.x * TILE_C;

    if (tid < TILE_C) s_M[tid] = -INFINITY;

    // load f0 tile -> xs (tf32-round, B-frag pack)
    const int c4   = tid & 15;
    const int prow = tid >> 4;
    for (int p = prow; p < PP; p += 16) {
        float4 v = *(const float4*)&facts[(size_t)p * CC + cbase + c4 * 4];
        const int k8 = p >> 3, pl = p & 3, ps = (p >> 2) & 1;
        const float vv[4] = {v.x, v.y, v.z, v.w};
        #pragma unroll
        for (int j = 0; j < 4; ++j) {
            const int c = c4 * 4 + j;
            const int idx = (((k8 << 3) | (c >> 3)) * 32 + ((c & 7) * 4 + pl)) * 2 + ps;
            xs[idx] = __uint_as_float(tf32r(vv[j]));
        }
    }
    __syncthreads();

    const int n_it = nit_ptr ? *nit_ptr : 3;
    const uint4*  A4  = (const uint4*)g_A;
    const float2* xs2 = (const float2*)xs;

    for (int it = 0; it < n_it; ++it) {
        float acc[4][8][4];
        #pragma unroll
        for (int mt = 0; mt < 4; ++mt)
            #pragma unroll
            for (int nt = 0; nt < 8; ++nt)
                #pragma unroll
                for (int q = 0; q < 4; ++q) acc[mt][nt][q] = 0.f;

        uint4 ap[2][4];
        #pragma unroll
        for (int mt = 0; mt < 4; ++mt)
            ap[0][mt] = A4[(size_t)((wid * 4 + mt) * 64 + 0) * 32 + lane];

        #pragma unroll 2
        for (int k8 = 0; k8 < 64; ++k8) {
            const int cur = k8 & 1, nxt = cur ^ 1;
            if (k8 + 1 < 64) {
                #pragma unroll
                for (int mt = 0; mt < 4; ++mt)
                    ap[nxt][mt] = A4[(size_t)((wid * 4 + mt) * 64 + (k8 + 1)) * 32 + lane];
            }
            float2 bf[8];
            #pragma unroll
            for (int nt = 0; nt < 8; ++nt)
                bf[nt] = xs2[(k8 * 8 + nt) * 32 + lane];

            #pragma unroll
            for (int mt = 0; mt < 4; ++mt) {
                const uint32_t a0 = ap[cur][mt].x, a1 = ap[cur][mt].y;
                const uint32_t a2 = ap[cur][mt].z, a3 = ap[cur][mt].w;
                #pragma unroll
                for (int nt = 0; nt < 8; ++nt) {
                    asm volatile(
                        "mma.sync.aligned.m16n8k8.row.col.f32.tf32.tf32.f32 "
                        "{%0,%1,%2,%3}, {%4,%5,%6,%7}, {%8,%9}, {%0,%1,%2,%3};"
                        : "+f"(acc[mt][nt][0]), "+f"(acc[mt][nt][1]),
                          "+f"(acc[mt][nt][2]), "+f"(acc[mt][nt][3])
                        : "r"(a0), "r"(a1), "r"(a2), "r"(a3),
                          "r"(__float_as_uint(bf[nt].x)),
                          "r"(__float_as_uint(bf[nt].y)));
                }
            }
        }

        // epilogue: column max. d-frag: row=(lane>>2)(+8), col=(lane&3)*2(+1)
        #pragma unroll
        for (int nt = 0; nt < 8; ++nt) {
            float m0 = -INFINITY, m1 = -INFINITY;
            #pragma unroll
            for (int mt = 0; mt < 4; ++mt) {
                m0 = fmaxf(m0, fmaxf(acc[mt][nt][0], acc[mt][nt][2]));
                m1 = fmaxf(m1, fmaxf(acc[mt][nt][1], acc[mt][nt][3]));
            }
            #pragma unroll
            for (int o = 4; o <= 16; o <<= 1) {
                m0 = fmaxf(m0, __shfl_xor_sync(0xffffffffu, m0, o));
                m1 = fmaxf(m1, __shfl_xor_sync(0xffffffffu, m1, o));
            }
            if (lane < 4) {
                s_red[wid][nt * 8 + lane * 2 + 0] = m0;
                s_red[wid][nt * 8 + lane * 2 + 1] = m1;
            }
        }
        __syncthreads();
        if (tid < TILE_C) {
            float mm = s_M[tid];
            #pragma unroll
            for (int w = 0; w < 8; ++w) mm = fmaxf(mm, s_red[w][tid]);
            s_M[tid] = mm;
        }
        __syncthreads();

        // fold M into xs for the next iteration: xs = max(xs, tf32(M[c]))
        if (it + 1 < n_it) {
            float2* xsw = (float2*)xs;
            for (int i2 = tid; i2 < PP * TILE_C / 2; i2 += NTHREADS) {
                const int c = (((i2 >> 5) & 7) << 3) | ((i2 & 31) >> 2);
                const float Mc = __uint_as_float(tf32r(s_M[c]));
                float2 v = xsw[i2];
                v.x = fmaxf(v.x, Mc);
                v.y = fmaxf(v.y, Mc);
                xsw[i2] = v;
            }
            __syncthreads();
        }
    }

    // output: max(exact f0, M_final), coalesced float4
    for (int p = prow; p < PP; p += 16) {
        float4 v = *(const float4*)&facts[(size_t)p * CC + cbase + c4 * 4];
        v.x = fmaxf(v.x, s_M[c4 * 4 + 0]);
        v.y = fmaxf(v.y, s_M[c4 * 4 + 1]);
        v.z = fmaxf(v.z, s_M[c4 * 4 + 2]);
        v.w = fmaxf(v.w, s_M[c4 * 4 + 3]);
        *(float4*)&out[(size_t)p * CC + cbase + c4 * 4] = v;
    }
}

// ---------------------------------------------------------------------------
extern "C" void kernel_launch(void* const* d_in, const int* in_sizes, int n_in,
                              void* d_out, int out_size) {
    (void)in_sizes; (void)out_size;
    const float* facts = (const float*)d_in[0];
    const float* rw    = (const float*)d_in[1];
    const int*   nit   = (n_in > 2) ? (const int*)d_in[2] : nullptr;
    float* out = (float*)d_out;

    cudaFuncSetAttribute(ilp_mma_kernel,
                         cudaFuncAttributeMaxDynamicSharedMemorySize, XS_BYTES);

    ilp_softmax_kernel<<<PP, NTHREADS>>>(rw);
    ilp_mma_kernel<<<CC / TILE_C, NTHREADS, XS_BYTES>>>(facts, nit, out);
}

// round 6
// speedup vs baseline: 4.5009x; 1.0846x over previous
#include <cuda_runtime.h>
#include <cstdint>
#include <cmath>

#define PP 512
#define CC 65536
#define TILE_C 32
#define NTHREADS 256
#define XS_BYTES (PP * TILE_C * 4)   // 64 KB

// A: softmaxed, tf32-rounded, stored in m16n8k8 A-fragment order:
//   g_A[(((m_tile*64) + k8)*32 + lane)*4 + slot],  slot = a0..a3
__device__ float g_A[PP * PP];

__device__ __forceinline__ uint32_t tf32r(float x) {
    uint32_t y;
    asm("cvt.rna.tf32.f32 %0, %1;" : "=r"(y) : "f"(x));
    return y;
}

// ---------------------------------------------------------------------------
// Kernel 1: softmax rows of rule_weights[r,0,:] -> g_A (tf32, frag-packed)
// ---------------------------------------------------------------------------
__global__ void ilp_softmax_kernel(const float* __restrict__ rw) {
    const int r = blockIdx.x;
    const int tid = threadIdx.x;
    const float* wrow = rw + r * PP;

    __shared__ float wbuf[8];
    __shared__ float s_mx, s_inv;

    float v0 = wrow[tid];
    float v1 = wrow[tid + 256];

    float m = fmaxf(v0, v1);
    #pragma unroll
    for (int o = 16; o; o >>= 1) m = fmaxf(m, __shfl_xor_sync(0xffffffffu, m, o));
    if ((tid & 31) == 0) wbuf[tid >> 5] = m;
    __syncthreads();
    if (tid == 0) {
        float mm = wbuf[0];
        #pragma unroll
        for (int w = 1; w < 8; ++w) mm = fmaxf(mm, wbuf[w]);
        s_mx = mm;
    }
    __syncthreads();

    float e0 = expf(v0 - s_mx);
    float e1 = expf(v1 - s_mx);
    float s = e0 + e1;
    #pragma unroll
    for (int o = 16; o; o >>= 1) s += __shfl_xor_sync(0xffffffffu, s, o);
    if ((tid & 31) == 0) wbuf[tid >> 5] = s;
    __syncthreads();
    if (tid == 0) {
        float ss = 0.f;
        #pragma unroll
        for (int w = 0; w < 8; ++w) ss += wbuf[w];
        s_inv = 1.0f / ss;
    }
    __syncthreads();

    const int mt = r >> 4;
    #pragma unroll
    for (int h = 0; h < 2; ++h) {
        const int p = tid + h * 256;                 // k index
        const float val = (h ? e1 : e0) * s_inv;
        const int k8   = p >> 3;
        const int lane = ((r & 7) << 2) | (p & 3);
        const int slot = ((r >> 3) & 1) | (((p >> 2) & 1) << 1);
        g_A[(((mt << 6) | k8) * 32 + lane) * 4 + slot] = __uint_as_float(tf32r(val));
    }
}

// ---------------------------------------------------------------------------
// Kernel 2: fused forward chaining via mma.sync m16n8k8 tf32.
//   CTA: 32 columns, 64 KB xs -> 2 CTAs/SM. Warp w covers rows [64w,64w+64):
//   4 m-tiles x 4 n-tiles -> 64 fp32 accumulators.
//   xs layout packs k8 PAIRS: [k16][nt][lane][4] so one LDS.128 feeds 2 steps.
// ---------------------------------------------------------------------------
__global__ void __launch_bounds__(NTHREADS, 2)
ilp_mma_kernel(const float* __restrict__ facts,
               const int* __restrict__ nit_ptr,
               float* __restrict__ out) {
    extern __shared__ float xs[];                    // [k16][nt][lane][4]
    __shared__ float s_M[TILE_C];
    __shared__ float s_red[8][TILE_C];

    const int tid  = threadIdx.x;
    const int wid  = tid >> 5;
    const int lane = tid & 31;
    const int cbase = blockIdx.x * TILE_C;

    if (tid < TILE_C) s_M[tid] = -INFINITY;

    // load f0 tile -> xs (tf32-round, paired-B-frag pack)
    const int c4   = tid & 7;                        // float4 col group (0..7)
    const int prow = tid >> 3;                       // 0..31
    for (int p = prow; p < PP; p += 32) {
        float4 v = *(const float4*)&facts[(size_t)p * CC + cbase + c4 * 4];
        const int k16 = p >> 4;
        const int slot = (((p >> 3) & 1) << 1) | ((p >> 2) & 1);
        const float vv[4] = {v.x, v.y, v.z, v.w};
        #pragma unroll
        for (int j = 0; j < 4; ++j) {
            const int c = c4 * 4 + j;
            const int ln = ((c & 7) << 2) | (p & 3);
            xs[(((k16 << 2) | (c >> 3)) * 32 + ln) * 4 + slot] =
                __uint_as_float(tf32r(vv[j]));
        }
    }
    __syncthreads();

    const int n_it = nit_ptr ? *nit_ptr : 3;
    const uint4*  A4  = (const uint4*)g_A;
    const float4* xs4 = (const float4*)xs;

    for (int it = 0; it < n_it; ++it) {
        float acc[4][4][4];
        #pragma unroll
        for (int mt = 0; mt < 4; ++mt)
            #pragma unroll
            for (int nt = 0; nt < 4; ++nt)
                #pragma unroll
                for (int q = 0; q < 4; ++q) acc[mt][nt][q] = 0.f;

        uint4 ap[2][4];
        #pragma unroll
        for (int mt = 0; mt < 4; ++mt)
            ap[0][mt] = A4[(size_t)((wid * 4 + mt) * 64 + 0) * 32 + lane];

        float4 bf[4];

        #pragma unroll 2
        for (int k8 = 0; k8 < 64; ++k8) {
            const int cur = k8 & 1, nxt = cur ^ 1;
            if (k8 + 1 < 64) {
                #pragma unroll
                for (int mt = 0; mt < 4; ++mt)
                    ap[nxt][mt] = A4[(size_t)((wid * 4 + mt) * 64 + (k8 + 1)) * 32 + lane];
            }
            if ((k8 & 1) == 0) {
                const int k16 = k8 >> 1;
                #pragma unroll
                for (int nt = 0; nt < 4; ++nt)
                    bf[nt] = xs4[(k16 * 4 + nt) * 32 + lane];
            }

            #pragma unroll
            for (int mt = 0; mt < 4; ++mt) {
                const uint32_t a0 = ap[cur][mt].x, a1 = ap[cur][mt].y;
                const uint32_t a2 = ap[cur][mt].z, a3 = ap[cur][mt].w;
                #pragma unroll
                for (int nt = 0; nt < 4; ++nt) {
                    const uint32_t b0 = __float_as_uint((k8 & 1) ? bf[nt].z : bf[nt].x);
                    const uint32_t b1 = __float_as_uint((k8 & 1) ? bf[nt].w : bf[nt].y);
                    asm volatile(
                        "mma.sync.aligned.m16n8k8.row.col.f32.tf32.tf32.f32 "
                        "{%0,%1,%2,%3}, {%4,%5,%6,%7}, {%8,%9}, {%0,%1,%2,%3};"
                        : "+f"(acc[mt][nt][0]), "+f"(acc[mt][nt][1]),
                          "+f"(acc[mt][nt][2]), "+f"(acc[mt][nt][3])
                        : "r"(a0), "r"(a1), "r"(a2), "r"(a3),
                          "r"(b0), "r"(b1));
                }
            }
        }

        // epilogue: column max. d-frag: row=(lane>>2)(+8), col=(lane&3)*2(+1)
        #pragma unroll
        for (int nt = 0; nt < 4; ++nt) {
            float m0 = -INFINITY, m1 = -INFINITY;
            #pragma unroll
            for (int mt = 0; mt < 4; ++mt) {
                m0 = fmaxf(m0, fmaxf(acc[mt][nt][0], acc[mt][nt][2]));
                m1 = fmaxf(m1, fmaxf(acc[mt][nt][1], acc[mt][nt][3]));
            }
            #pragma unroll
            for (int o = 4; o <= 16; o <<= 1) {
                m0 = fmaxf(m0, __shfl_xor_sync(0xffffffffu, m0, o));
                m1 = fmaxf(m1, __shfl_xor_sync(0xffffffffu, m1, o));
            }
            if (lane < 4) {
                s_red[wid][nt * 8 + lane * 2 + 0] = m0;
                s_red[wid][nt * 8 + lane * 2 + 1] = m1;
            }
        }
        __syncthreads();
        if (tid < TILE_C) {
            float mm = s_M[tid];
            #pragma unroll
            for (int w = 0; w < 8; ++w) mm = fmaxf(mm, s_red[w][tid]);
            s_M[tid] = mm;
        }
        __syncthreads();

        // fold M into xs for the next iteration: xs = max(xs, tf32(M[c]))
        if (it + 1 < n_it) {
            float2* xsw = (float2*)xs;
            for (int i2 = tid; i2 < PP * TILE_C / 2; i2 += NTHREADS) {
                // i2 -> [k16][nt][lane][pair]; c = nt*8 + (lane>>2)
                const int c = (((i2 >> 6) & 3) << 3) | ((i2 >> 3) & 7);
                const float Mc = __uint_as_float(tf32r(s_M[c]));
                float2 v = xsw[i2];
                v.x = fmaxf(v.x, Mc);
                v.y = fmaxf(v.y, Mc);
                xsw[i2] = v;
            }
            __syncthreads();
        }
    }

    // output: max(exact f0, M_final), coalesced float4
    for (int p = prow; p < PP; p += 32) {
        float4 v = *(const float4*)&facts[(size_t)p * CC + cbase + c4 * 4];
        v.x = fmaxf(v.x, s_M[c4 * 4 + 0]);
        v.y = fmaxf(v.y, s_M[c4 * 4 + 1]);
        v.z = fmaxf(v.z, s_M[c4 * 4 + 2]);
        v.w = fmaxf(v.w, s_M[c4 * 4 + 3]);
        *(float4*)&out[(size_t)p * CC + cbase + c4 * 4] = v;
    }
}

// ---------------------------------------------------------------------------
extern "C" void kernel_launch(void* const* d_in, const int* in_sizes, int n_in,
                              void* d_out, int out_size) {
    (void)in_sizes; (void)out_size;
    const float* facts = (const float*)d_in[0];
    const float* rw    = (const float*)d_in[1];
    const int*   nit   = (n_in > 2) ? (const int*)d_in[2] : nullptr;
    float* out = (float*)d_out;

    cudaFuncSetAttribute(ilp_mma_kernel,
                         cudaFuncAttributeMaxDynamicSharedMemorySize, XS_BYTES);

    ilp_softmax_kernel<<<PP, NTHREADS>>>(rw);
    ilp_mma_kernel<<<CC / TILE_C, NTHREADS, XS_BYTES>>>(facts, nit, out);
}

// round 7
// speedup vs baseline: 7.9623x; 1.7690x over previous
#include <cuda_runtime.h>
#include <cuda_fp16.h>
#include <cstdint>
#include <cmath>

#define PP 512
#define CC 65536
#define TILE_C 32
#define NTHREADS 256

// A: softmaxed, fp16-rounded, packed in m16n8k16 A-fragment order:
//   g_A[(((mt*32 + k16)*32 + lane)*4 + regidx]  (uint32 = fp16x2)
//   regidx = (row_in>>3) | (((k_local>>3)&1)<<1), halves = k&1
__device__ uint32_t g_A[PP * PP / 2];

// ---------------------------------------------------------------------------
// Kernel 1: softmax rows of rule_weights[r,0,:] -> g_A (fp16x2, frag-packed)
// ---------------------------------------------------------------------------
__global__ void ilp_softmax_kernel(const float* __restrict__ rw) {
    const int r = blockIdx.x;
    const int tid = threadIdx.x;
    const float* wrow = rw + r * PP;

    __shared__ float wbuf[8];
    __shared__ float s_mx, s_inv;

    // thread t handles k = 2t, 2t+1 (one fp16x2 output word)
    float2 v = *(const float2*)&wrow[2 * tid];

    float m = fmaxf(v.x, v.y);
    #pragma unroll
    for (int o = 16; o; o >>= 1) m = fmaxf(m, __shfl_xor_sync(0xffffffffu, m, o));
    if ((tid & 31) == 0) wbuf[tid >> 5] = m;
    __syncthreads();
    if (tid == 0) {
        float mm = wbuf[0];
        #pragma unroll
        for (int w = 1; w < 8; ++w) mm = fmaxf(mm, wbuf[w]);
        s_mx = mm;
    }
    __syncthreads();

    float e0 = expf(v.x - s_mx);
    float e1 = expf(v.y - s_mx);
    float s = e0 + e1;
    #pragma unroll
    for (int o = 16; o; o >>= 1) s += __shfl_xor_sync(0xffffffffu, s, o);
    if ((tid & 31) == 0) wbuf[tid >> 5] = s;
    __syncthreads();
    if (tid == 0) {
        float ss = 0.f;
        #pragma unroll
        for (int w = 0; w < 8; ++w) ss += wbuf[w];
        s_inv = 1.0f / ss;
    }
    __syncthreads();

    const int mt     = r >> 4;
    const int row_in = r & 15;
    const int k16    = tid >> 3;
    const int lane   = ((row_in & 7) << 2) | (tid & 3);
    const int regidx = ((row_in >> 3) & 1) | (((tid >> 2) & 1) << 1);

    __half2 h2 = __floats2half2_rn(e0 * s_inv, e1 * s_inv);
    g_A[(((mt * 32 + k16) * 32 + lane) << 2) | regidx] =
        *(const uint32_t*)&h2;
}

// ---------------------------------------------------------------------------
// Kernel 2: fused forward chaining via mma.sync m16n8k16 f16 (fp32 accum).
//   CTA: 32 columns, xs 32KB fp16 -> 2 CTAs/SM. Warp w: rows [64w,64w+64):
//   4 m-tiles x 4 n-tiles -> 64 fp32 accumulators, 16 MMAs per k16 step.
//   xs layout: [k16][ntp][lane][q] uint32, q = (nt&1)*2 + bpair.
// ---------------------------------------------------------------------------
__global__ void __launch_bounds__(NTHREADS, 2)
ilp_mma_kernel(const float* __restrict__ facts,
               const int* __restrict__ nit_ptr,
               float* __restrict__ out) {
    __shared__ __align__(16) uint32_t xs[PP * TILE_C / 2];  // 32 KB fp16
    __shared__ float s_M[TILE_C];
    __shared__ float s_red[8][TILE_C];

    const int tid  = threadIdx.x;
    const int wid  = tid >> 5;
    const int lane = tid & 31;
    const int cbase = blockIdx.x * TILE_C;

    if (tid < TILE_C) s_M[tid] = -INFINITY;

    // load f0 tile -> xs (fp16-round, B-frag pack)
    const int c4   = tid & 7;                        // float4 col group (0..7)
    const int prow = tid >> 3;                       // 0..31
    __half* xsh = (__half*)xs;
    for (int p = prow; p < PP; p += 32) {
        float4 v = *(const float4*)&facts[(size_t)p * CC + cbase + c4 * 4];
        const int k16 = p >> 4;
        const int bp  = (p >> 3) & 1;
        const int ln  = (p >> 1) & 3;                // k-part of lane
        const int hf  = p & 1;
        const float vv[4] = {v.x, v.y, v.z, v.w};
        #pragma unroll
        for (int j = 0; j < 4; ++j) {
            const int c = c4 * 4 + j;
            const int lane_d = ((c & 7) << 2) | ln;
            const int ntp = (c >> 4) & 1;
            const int q = (((c >> 3) & 1) << 1) | bp;
            xsh[((((k16 * 2 + ntp) * 32 + lane_d) << 2) | q) * 2 + hf] =
                __float2half_rn(vv[j]);
        }
    }
    __syncthreads();

    const int n_it = nit_ptr ? *nit_ptr : 3;
    const uint4* A4  = (const uint4*)g_A;
    const uint4* xs4 = (const uint4*)xs;

    for (int it = 0; it < n_it; ++it) {
        float acc[4][4][4];
        #pragma unroll
        for (int mt = 0; mt < 4; ++mt)
            #pragma unroll
            for (int nt = 0; nt < 4; ++nt)
                #pragma unroll
                for (int q = 0; q < 4; ++q) acc[mt][nt][q] = 0.f;

        uint4 ap[2][4];
        #pragma unroll
        for (int mt = 0; mt < 4; ++mt)
            ap[0][mt] = A4[(size_t)((wid * 4 + mt) * 32 + 0) * 32 + lane];

        #pragma unroll 2
        for (int k16 = 0; k16 < 32; ++k16) {
            const int cur = k16 & 1, nxt = cur ^ 1;
            if (k16 + 1 < 32) {
                #pragma unroll
                for (int mt = 0; mt < 4; ++mt)
                    ap[nxt][mt] =
                        A4[(size_t)((wid * 4 + mt) * 32 + (k16 + 1)) * 32 + lane];
            }
            uint4 bf[2];
            #pragma unroll
            for (int ntp = 0; ntp < 2; ++ntp)
                bf[ntp] = xs4[(k16 * 2 + ntp) * 32 + lane];

            #pragma unroll
            for (int mt = 0; mt < 4; ++mt) {
                const uint32_t a0 = ap[cur][mt].x, a1 = ap[cur][mt].y;
                const uint32_t a2 = ap[cur][mt].z, a3 = ap[cur][mt].w;
                #pragma unroll
                for (int nt = 0; nt < 4; ++nt) {
                    const uint32_t b0 = (nt & 1) ? ((nt >> 1) ? bf[1].z : bf[0].z)
                                                 : ((nt >> 1) ? bf[1].x : bf[0].x);
                    const uint32_t b1 = (nt & 1) ? ((nt >> 1) ? bf[1].w : bf[0].w)
                                                 : ((nt >> 1) ? bf[1].y : bf[0].y);
                    asm volatile(
                        "mma.sync.aligned.m16n8k16.row.col.f32.f16.f16.f32 "
                        "{%0,%1,%2,%3}, {%4,%5,%6,%7}, {%8,%9}, {%0,%1,%2,%3};"
                        : "+f"(acc[mt][nt][0]), "+f"(acc[mt][nt][1]),
                          "+f"(acc[mt][nt][2]), "+f"(acc[mt][nt][3])
                        : "r"(a0), "r"(a1), "r"(a2), "r"(a3),
                          "r"(b0), "r"(b1));
                }
            }
        }

        // epilogue: column max. d-frag: row=(lane>>2)(+8), col=(lane&3)*2(+1)
        // NOTE: nt here indexes 8-col groups; q>>1 selects ntp, consistent
        // with xs layout: nt_logical = ntp*2 + (q>>1) -> cols nt_logical*8+..
        #pragma unroll
        for (int nt = 0; nt < 4; ++nt) {
            // logical column group of acc[..][nt]: ntl = (nt>>1)*2 + (nt&1)
            float m0 = -INFINITY, m1 = -INFINITY;
            #pragma unroll
            for (int mt = 0; mt < 4; ++mt) {
                m0 = fmaxf(m0, fmaxf(acc[mt][nt][0], acc[mt][nt][2]));
                m1 = fmaxf(m1, fmaxf(acc[mt][nt][1], acc[mt][nt][3]));
            }
            #pragma unroll
            for (int o = 4; o <= 16; o <<= 1) {
                m0 = fmaxf(m0, __shfl_xor_sync(0xffffffffu, m0, o));
                m1 = fmaxf(m1, __shfl_xor_sync(0xffffffffu, m1, o));
            }
            if (lane < 4) {
                const int ntl = ((nt >> 1) << 1) | (nt & 1);  // == nt
                s_red[wid][ntl * 8 + lane * 2 + 0] = m0;
                s_red[wid][ntl * 8 + lane * 2 + 1] = m1;
            }
        }
        __syncthreads();
        if (tid < TILE_C) {
            float mm = s_M[tid];
            #pragma unroll
            for (int w = 0; w < 8; ++w) mm = fmaxf(mm, s_red[w][tid]);
            s_M[tid] = mm;
        }
        __syncthreads();

        // fold M into xs: xs = hmax2(xs, fp16(M[c]))
        if (it + 1 < n_it) {
            for (int i = tid; i < PP * TILE_C / 2; i += NTHREADS) {
                const int q   = i & 3;
                const int ntp = (i >> 7) & 1;
                const int c   = (((ntp << 1) | (q >> 1)) << 3) | ((i >> 4) & 7);
                __half2 mc2 = __float2half2_rn(s_M[c]);
                __half2 v = *(__half2*)&xs[i];
                v = __hmax2(v, mc2);
                xs[i] = *(uint32_t*)&v;
            }
            __syncthreads();
        }
    }

    // output: max(exact f0, M_final), coalesced float4
    for (int p = prow; p < PP; p += 32) {
        float4 v = *(const float4*)&facts[(size_t)p * CC + cbase + c4 * 4];
        v.x = fmaxf(v.x, s_M[c4 * 4 + 0]);
        v.y = fmaxf(v.y, s_M[c4 * 4 + 1]);
        v.z = fmaxf(v.z, s_M[c4 * 4 + 2]);
        v.w = fmaxf(v.w, s_M[c4 * 4 + 3]);
        *(float4*)&out[(size_t)p * CC + cbase + c4 * 4] = v;
    }
}

// ---------------------------------------------------------------------------
extern "C" void kernel_launch(void* const* d_in, const int* in_sizes, int n_in,
                              void* d_out, int out_size) {
    (void)in_sizes; (void)out_size;
    const float* facts = (const float*)d_in[0];
    const float* rw    = (const float*)d_in[1];
    const int*   nit   = (n_in > 2) ? (const int*)d_in[2] : nullptr;
    float* out = (float*)d_out;

    ilp_softmax_kernel<<<PP, NTHREADS>>>(rw);
    ilp_mma_kernel<<<CC / TILE_C, NTHREADS>>>(facts, nit, out);
}